// round 14
// baseline (speedup 1.0000x reference)
#include <cuda_runtime.h>
#include <math.h>

// ---------------------------------------------------------------------------
// DilatedSparseRnnStack — R14: symmetric CTA pairs, 16 rows/group, K-split.
// Each CTA of a pair reads only HALF the weights (chip weight traffic
// 805 -> 403 MB/step, dropping below the measured LTS cap that bound R8-R13).
// Rank r handles k-half r of all 1024 gate-cols for 16 batch rows; k-partials
// for the partner-owned 8 rows are exchanged through an L2 box with windowed
// monotonic flags (symmetric, near-zero skew). Epilogue ownership by rows:
// rank0 rows 0-7, rank1 rows 8-15. out-section lives entirely in rank0's
// k-half; rank1 publishes its out rows via g_out. fp32 math unchanged.
// ---------------------------------------------------------------------------

namespace {
constexpr int T_STEPS = 256;
constexpr int BATCH   = 1024;
constexpr int IN_F    = 64;
constexpr int HSZ     = 128;
constexpr int OSZ     = 128;
constexpr int OUT_F   = 8;
constexpr int RPG     = 16;             // rows per group
constexpr int NGRP    = BATCH / RPG;    // 64
constexpr int NCTA    = NGRP * 2;       // 128
constexpr int NTHR    = 512;
constexpr int KTOT    = 320 + 384 + 448 + 384;  // 1536

// dynamic SMEM layout (bytes); xh buffer holds this CTA's k-half: [kloc][16 r]
constexpr int SM_XH0   = 0;        // 224*64 = 14336 (max K/2)
constexpr int SM_XH1   = 14336;
constexpr int SM_RED   = 28672;    // 256 j * 2 gp * 4 ull * 8B = 16384
constexpr int SM_OUT   = 45056;    // 128*8*4 = 4096 (own 8 rows)
constexpr int SM_WOUT  = 49152;    // 4096
constexpr int SM_TOTAL = 53248;
}

// Weights, transposed + gate-pair interleaved:
// float at WTOFF + ((k*2 + gp)*256 + j)*2 + gl   (gate g = 2*gp + gl)
// padded 8192 floats so the ring prefetch may harmlessly over-read.
__device__ float g_WT2[(size_t)KTOT * 1024 + 8192];

// Dilation buffers, group-local (slot offsets {0,1,4,10}, sizes {1,3,6,12}):
//   C: [slot 22][group 64][j 256][r 16]  (float4 quad rq = rows 4rq..4rq+3)
//   H: [slot 22][group 64][jh 128][r 16]
__device__ float4 g_bufC4[(size_t)22 * 64 * 256 * 4];
__device__ float4 g_bufH4[(size_t)22 * 64 * 128 * 4];

// out exchange (rank1 -> rank0): [group][j 128][quad 2] (rows 8-11, 12-15)
__device__ float4 g_out4[(size_t)64 * 128 * 2];

// k-partials exchange: [group][src 2][gp*256+j][8 ull]
__device__ unsigned long long g_part[(size_t)64 * 2 * 512 * 8];

// lockstep counters (monotonic within a launch; windowed reads)
__device__ int g_cntP[64][2];
__device__ int g_cntE[64][2];

__device__ __forceinline__ float sigf(float v) {
    return __fdividef(1.0f, 1.0f + __expf(-v));
}
__device__ __forceinline__ float tanh_fast(float v) {
    return __fdividef(2.0f, 1.0f + __expf(-2.0f * v)) - 1.0f;
}
__device__ __forceinline__ void ffma2(unsigned long long& d,
                                      unsigned long long a,
                                      unsigned long long b) {
    asm("fma.rn.f32x2 %0, %1, %2, %0;" : "+l"(d) : "l"(a), "l"(b));
}
__device__ __forceinline__ void fadd2(unsigned long long& d,
                                      unsigned long long a) {
    asm("add.rn.f32x2 %0, %0, %1;" : "+l"(d) : "l"(a));
}
__device__ __forceinline__ unsigned long long dup2(float w) {
    unsigned long long r;
    asm("mov.b64 %0, {%1, %1};" : "=l"(r) : "f"(w));
    return r;
}
__device__ __forceinline__ float2 u2f2(unsigned long long v) {
    float2 f;
    asm("mov.b64 {%0, %1}, %2;" : "=f"(f.x), "=f"(f.y) : "l"(v));
    return f;
}
// all threads spin; windowed check rejects stale cross-replay values (max 1024)
__device__ __forceinline__ void spin_ge(const int* f, int need) {
    unsigned it = 0;
    int v;
    do {
        asm volatile("ld.acquire.gpu.b32 %0, [%1];" : "=r"(v) : "l"(f));
        if (v >= need && v < need + 256) return;
    } while (++it < (1u << 22));
}
__device__ __forceinline__ void set_flag(int* f, int v) {
    asm volatile("st.release.gpu.b32 [%0], %1;" :: "l"(f), "r"(v) : "memory");
}

// ---------------------------------------------------------------------------
// Prep: transpose + gate-pair interleave weights.
// ---------------------------------------------------------------------------
__global__ void prep_kernel(const float* __restrict__ W0,
                            const float* __restrict__ W1,
                            const float* __restrict__ W2,
                            const float* __restrict__ W3)
{
    const int li = blockIdx.y;
    const float* W;
    int K, off;
    if (li == 0)      { W = W0; K = 320; off = 0; }
    else if (li == 1) { W = W1; K = 384; off = 320 * 1024; }
    else if (li == 2) { W = W2; K = 448; off = 704 * 1024; }
    else              { W = W3; K = 384; off = 1152 * 1024; }

    int idx = blockIdx.x * 256 + threadIdx.x;
    if (idx < 1024 * K) {
        int row = idx / K;           // g*256 + j
        int k   = idx - row * K;
        int g = row >> 8, j = row & 255;
        g_WT2[(size_t)off + ((size_t)(k * 2 + (g >> 1)) * 256 + j) * 2 + (g & 1)]
            = W[idx];
    }
}

// ---------------------------------------------------------------------------
// staging helpers
// ---------------------------------------------------------------------------
__device__ __forceinline__ void stage_Hsec(
    float* __restrict__ xh, int tid, int group, int slot, bool zero,
    int C0, int C1, int DST)
{
    const int n4 = (C1 - C0) * 4;
    for (int e = tid; e < n4; e += NTHR) {
        int jh = C0 + (e >> 2), rq = e & 3;
        float4 v = make_float4(0.f, 0.f, 0.f, 0.f);
        if (!zero)
            v = g_bufH4[((size_t)(slot * 64 + group) * 128 + jh) * 4 + rq];
        *reinterpret_cast<float4*>(&xh[(DST + (jh - C0)) * 16 + rq * 4]) = v;
    }
}
__device__ __forceinline__ void stage_xsec(
    float* __restrict__ xh, int tid, const float4* __restrict__ xt4, int DST)
{
    if (tid < 256) {
        int c4 = tid >> 4, r = tid & 15;
        float4 v = xt4[r * 16 + c4];
        int b = (DST + 4 * c4) * 16 + r;
        xh[b]      = v.x;
        xh[b + 16] = v.y;
        xh[b + 32] = v.z;
        xh[b + 48] = v.w;
    }
}
__device__ __forceinline__ void stage_outsec(
    float* __restrict__ xh, int tid, int group)
{
    if (tid < 256) {
        int jo = tid >> 1, q = tid & 1;
        *reinterpret_cast<float4*>(&xh[jo * 16 + (2 + q) * 4]) =
            g_out4[(size_t)(group * 128 + jo) * 2 + q];
    }
}

// ---------------------------------------------------------------------------
// One layer step. thread: j = tid&255 (col), gp = tid>>8 (gate pair).
// This CTA computes k-half `rank` of all gates for 16 rows; owns rows
// [8*rank, 8*rank+8) for the epilogue.
// ---------------------------------------------------------------------------
template <int K, int DIL, int LOFF, int LI, int WTOFF>
__device__ __forceinline__ void do_layer(
    int t, int tid, int group, int rank,
    const float4* __restrict__ xt4,
    float4 bias,
    char* __restrict__ smem)
{
    const int prevSlot = LOFF + (t - 1 + DIL) % DIL;
    const int curSlot  = LOFF + (t % DIL);
    const int j    = tid & 255;
    const int gp   = tid >> 8;
    const int m    = 4 * t + LI;
    constexpr int KH = K / 2;

    float* xh = reinterpret_cast<float*>(smem + ((LI & 1) ? SM_XH1 : SM_XH0));
    unsigned long long* s_red =
        reinterpret_cast<unsigned long long*>(smem + SM_RED);
    float* s_out = reinterpret_cast<float*>(smem + SM_OUT);

    // ---- wait partner epilogue of phase m-1 (H / g_out / box-consume) ----
    if (m > 0) spin_ge(&g_cntE[group][1 - rank], m);

    // ---- C prefetch (own quad; written only by this thread historically) ----
    const int quad = 2 * rank + gp;
    const size_t cI = ((size_t)(curSlot  * 64 + group) * 256 + j) * 4 + quad;
    const size_t pI = ((size_t)(prevSlot * 64 + group) * 256 + j) * 4 + quad;
    float4 pC4 = make_float4(0.f, 0.f, 0.f, 0.f);
    float4 dC4 = make_float4(0.f, 0.f, 0.f, 0.f);
    if (t > 0)    pC4 = g_bufC4[pI];
    if (t >= DIL) dC4 = g_bufC4[cI];

    // ---- weight ring prologue (addresses independent of staging) ----
    const char* wp = reinterpret_cast<const char*>(g_WT2)
                   + (size_t)WTOFF * 4 + (size_t)j * 8 + (size_t)gp * 2048
                   + (size_t)rank * KH * 4096;
    float2 wr[8];
#pragma unroll
    for (int u = 0; u < 8; ++u)
        wr[u] = *reinterpret_cast<const float2*>(wp + u * 4096);

    // ---- stage this CTA's k-half of xh ----
    {
        const int slotD = (t >= DIL) ? curSlot : prevSlot;
        const bool z = (t == 0);
        if (rank == 0) {
            if (LI == 0) {
                stage_xsec(xh, tid, xt4, 0);
                stage_Hsec(xh, tid, group, prevSlot, z, 0, 96, 64);
            } else if (LI == 2) {
                stage_outsec(xh, tid, group);
                stage_xsec(xh, tid, xt4, 128);
                stage_Hsec(xh, tid, group, prevSlot, z, 0, 32, 192);
            } else {  // LI 1,3
                stage_outsec(xh, tid, group);
                stage_Hsec(xh, tid, group, prevSlot, z, 0, 64, 128);
            }
        } else {
            if (LI == 0) {
                stage_Hsec(xh, tid, group, prevSlot, z, 96, 128, 0);
                stage_Hsec(xh, tid, group, slotD,    z, 0, 128, 32);
            } else if (LI == 2) {
                stage_Hsec(xh, tid, group, prevSlot, z, 32, 128, 0);
                stage_Hsec(xh, tid, group, slotD,    z, 0, 128, 96);
            } else {
                stage_Hsec(xh, tid, group, prevSlot, z, 64, 128, 0);
                stage_Hsec(xh, tid, group, slotD,    z, 0, 128, 64);
            }
        }
    }

    __syncthreads();  // sync B: xh k-half complete (incl. direct out-writes)

    // ---- GEMM: gates {2gp,2gp+1} x 16 rows over k-half ----
    unsigned long long aL[8], aH[8];
#pragma unroll
    for (int p = 0; p < 8; ++p) { aL[p] = 0ull; aH[p] = 0ull; }

    {
        const char* xp = reinterpret_cast<const char*>(xh);
        for (int kb = 0; kb < KH; kb += 8) {
#pragma unroll
            for (int u = 0; u < 8; ++u) {
                float2 w = wr[u];
                wr[u] = *reinterpret_cast<const float2*>(wp + (u + 8) * 4096);
                unsigned long long wA = dup2(w.x);
                unsigned long long wB = dup2(w.y);
                ulonglong2 x0 = *reinterpret_cast<const ulonglong2*>(xp + u * 64);
                ulonglong2 x1 = *reinterpret_cast<const ulonglong2*>(xp + u * 64 + 16);
                ffma2(aL[0], wA, x0.x); ffma2(aH[0], wB, x0.x);
                ffma2(aL[1], wA, x0.y); ffma2(aH[1], wB, x0.y);
                ffma2(aL[2], wA, x1.x); ffma2(aH[2], wB, x1.x);
                ffma2(aL[3], wA, x1.y); ffma2(aH[3], wB, x1.y);
                ulonglong2 x2 = *reinterpret_cast<const ulonglong2*>(xp + u * 64 + 32);
                ulonglong2 x3 = *reinterpret_cast<const ulonglong2*>(xp + u * 64 + 48);
                ffma2(aL[4], wA, x2.x); ffma2(aH[4], wB, x2.x);
                ffma2(aL[5], wA, x2.y); ffma2(aH[5], wB, x2.y);
                ffma2(aL[6], wA, x3.x); ffma2(aH[6], wB, x3.x);
                ffma2(aL[7], wA, x3.y); ffma2(aH[7], wB, x3.y);
            }
            wp += 8 * 4096;
            xp += 8 * 64;
        }
    }

    // ---- publish partials for partner-owned row-pairs ----
    {
        const int pn = 4 * (1 - rank);
        ulonglong2* b2 = reinterpret_cast<ulonglong2*>(
            g_part + ((size_t)(group * 2 + rank) * 512 + gp * 256 + j) * 8);
        b2[0] = make_ulonglong2(aL[pn],     aL[pn + 1]);
        b2[1] = make_ulonglong2(aL[pn + 2], aL[pn + 3]);
        b2[2] = make_ulonglong2(aH[pn],     aH[pn + 1]);
        b2[3] = make_ulonglong2(aH[pn + 2], aH[pn + 3]);
    }
    __threadfence();
    __syncthreads();  // sync X: all partial STGs issued + fenced
    if (tid == 0) set_flag(&g_cntP[group][rank], m + 1);

    spin_ge(&g_cntP[group][1 - rank], m + 1);

    // ---- fold partner partials into my owned pairs ----
    {
        const int po = 4 * rank;
        const ulonglong2* b2 = reinterpret_cast<const ulonglong2*>(
            g_part + ((size_t)(group * 2 + (1 - rank)) * 512 + gp * 256 + j) * 8);
        ulonglong2 v0 = b2[0], v1 = b2[1], v2 = b2[2], v3 = b2[3];
        fadd2(aL[po],     v0.x); fadd2(aL[po + 1], v0.y);
        fadd2(aL[po + 2], v1.x); fadd2(aL[po + 3], v1.y);
        fadd2(aH[po],     v2.x); fadd2(aH[po + 1], v2.y);
        fadd2(aH[po + 2], v3.x); fadd2(aH[po + 3], v3.y);
    }

    // ---- intra-CTA gate regroup via s_red ----
    {
        const int pw = 4 * rank + 2 * (1 - gp);   // other sub-owner's pairs
        ulonglong2* r2 = reinterpret_cast<ulonglong2*>(
            s_red + (size_t)(j * 2 + gp) * 4);
        r2[0] = make_ulonglong2(aL[pw], aL[pw + 1]);
        r2[1] = make_ulonglong2(aH[pw], aH[pw + 1]);
    }
    __syncthreads();  // sync D
    unsigned long long oG0, oG1, oG2, oG3;
    {
        const ulonglong2* r2 = reinterpret_cast<const ulonglong2*>(
            s_red + (size_t)(j * 2 + (1 - gp)) * 4);
        ulonglong2 q0 = r2[0], q1 = r2[1];
        oG0 = q0.x; oG1 = q0.y; oG2 = q1.x; oG3 = q1.y;
    }

    // ---- select the 4 gates for my 2 owned pairs ----
    const int p0 = 4 * rank + 2 * gp;
    unsigned long long Gf[2], Gc[2], Ga[2], Go[2];
    if (gp == 0) {
        Gf[0] = aL[p0]; Gf[1] = aL[p0 + 1];
        Gc[0] = aH[p0]; Gc[1] = aH[p0 + 1];
        Ga[0] = oG0;    Ga[1] = oG1;
        Go[0] = oG2;    Go[1] = oG3;
    } else {
        Ga[0] = aL[p0]; Ga[1] = aL[p0 + 1];
        Go[0] = aH[p0]; Go[1] = aH[p0 + 1];
        Gf[0] = oG0;    Gf[1] = oG1;
        Gc[0] = oG2;    Gc[1] = oG3;
    }

    // ---- epilogue: 4 rows (quad) of col j ----
    const float* pCf = &pC4.x;
    const float* dCf = &dC4.x;
    float nc[4], wh[4];
#pragma unroll
    for (int i = 0; i < 2; ++i) {
        float2 g0 = u2f2(Gf[i]);
        float2 g1 = u2f2(Gc[i]);
        float2 g2 = u2f2(Ga[i]);
        float2 g3 = u2f2(Go[i]);
#pragma unroll
        for (int s = 0; s < 2; ++s) {
            const int r = 2 * i + s;
            float forget = sigf((s ? g0.y : g0.x) + bias.x + 1.0f);
            float cand   = tanh_fast((s ? g1.y : g1.x) + bias.y);
            float alpha  = sigf((s ? g2.y : g2.x) + bias.z);
            float og     = sigf((s ? g3.y : g3.x) + bias.w);
            float newC;
            if (t == 0) {
                newC = cand;
            } else {
                float wC = pCf[r];
                if (t >= DIL) {
                    wC = alpha * pCf[r] + (1.0f - alpha) * dCf[r];
                }
                newC = forget * wC + (1.0f - forget) * cand;
            }
            nc[r] = newC;
            wh[r] = og * newC;
        }
    }
    g_bufC4[cI] = make_float4(nc[0], nc[1], nc[2], nc[3]);
    float4 w4 = make_float4(wh[0], wh[1], wh[2], wh[3]);
    if (j < OSZ) {
        if (LI < 3) {
            if (rank == 0) {
                // own rows 0-7 (quads 0,1) directly into next xh buffer
                float* xn = reinterpret_cast<float*>(
                    smem + ((LI & 1) ? SM_XH0 : SM_XH1));
                *reinterpret_cast<float4*>(&xn[j * 16 + quad * 4]) = w4;
            } else {
                g_out4[(size_t)(group * 128 + j) * 2 + gp] = w4;
            }
        } else {
            *reinterpret_cast<float4*>(&s_out[j * 8 + gp * 4]) = w4;
        }
    } else {
        g_bufH4[((size_t)(curSlot * 64 + group) * 128 + (j - OSZ)) * 4 + quad] = w4;
    }

    __threadfence();
    __syncthreads();  // sync F: all epilogue STGs issued + fenced
    if (tid == 0) set_flag(&g_cntE[group][rank], m + 1);
}

__global__ __launch_bounds__(NTHR, 1) void rnn_stack_kernel(
    const float* __restrict__ x,
    const float* __restrict__ b0, const float* __restrict__ b1,
    const float* __restrict__ b2, const float* __restrict__ b3,
    const float* __restrict__ Wout, const float* __restrict__ bout,
    float* __restrict__ out)
{
    extern __shared__ char smem[];
    float* s_out  = reinterpret_cast<float*>(smem + SM_OUT);
    float* s_wout = reinterpret_cast<float*>(smem + SM_WOUT);

    const int tid   = threadIdx.x;
    const int group = blockIdx.x >> 1;
    const int rank  = blockIdx.x & 1;
    const int row0  = group * RPG;
    const int j     = tid & 255;

    // reset own counters for this launch/replay
    if (tid == 0) {
        g_cntP[group][rank] = 0;
        g_cntE[group][rank] = 0;
        __threadfence();
    }

    if (tid < 256) {
        reinterpret_cast<float4*>(s_wout)[tid] =
            reinterpret_cast<const float4*>(Wout)[tid];
    }
    float4 bs0 = make_float4(b0[j], b0[256 + j], b0[512 + j], b0[768 + j]);
    float4 bs1 = make_float4(b1[j], b1[256 + j], b1[512 + j], b1[768 + j]);
    float4 bs2 = make_float4(b2[j], b2[256 + j], b2[512 + j], b2[768 + j]);
    float4 bs3 = make_float4(b3[j], b3[256 + j], b3[512 + j], b3[768 + j]);

    // projection mapping over own 8 rows: seg=tid&7, o=(tid>>3)&7, r=tid>>6
    const int p_seg = tid & 7;
    const int p_o   = (tid >> 3) & 7;
    const int p_r   = tid >> 6;
    const float bo  = bout[p_o];

    __syncthreads();  // counters reset + s_wout staged

    for (int t = 0; t < T_STEPS; ++t) {
        const float4* xt4 = reinterpret_cast<const float4*>(
            x + ((size_t)t * BATCH + row0) * IN_F);

        do_layer<320,  1,  0, 0, 0>          (t, tid, group, rank, xt4, bs0, smem);
        do_layer<384,  3,  1, 1, 320 * 1024> (t, tid, group, rank, xt4, bs1, smem);
        do_layer<448,  6,  4, 2, 704 * 1024> (t, tid, group, rank, xt4, bs2, smem);
        do_layer<384, 12, 10, 3, 1152 * 1024>(t, tid, group, rank, xt4, bs3, smem);

        // ---- output projection over own 8 rows (s_out fenced by sync F) ----
        {
            float acc = 0.f;
#pragma unroll
            for (int qq = 0; qq < 16; ++qq) {
                int qv = qq * 8 + p_seg;
                acc = fmaf(s_out[qv * 8 + p_r], s_wout[p_o * OSZ + qv], acc);
            }
            acc += __shfl_down_sync(0xffffffffu, acc, 4, 8);
            acc += __shfl_down_sync(0xffffffffu, acc, 2, 8);
            acc += __shfl_down_sync(0xffffffffu, acc, 1, 8);
            if (p_seg == 0) {
                out[((size_t)t * BATCH + row0 + 8 * rank + p_r) * OUT_F + p_o]
                    = acc + bo;
            }
        }
    }
}

extern "C" void kernel_launch(void* const* d_in, const int* in_sizes, int n_in,
                              void* d_out, int out_size)
{
    (void)in_sizes; (void)n_in; (void)out_size;

    cudaFuncSetAttribute(rnn_stack_kernel,
                         cudaFuncAttributeMaxDynamicSharedMemorySize, SM_TOTAL);

    dim3 pgrid((1024 * 448 + 255) / 256, 4);
    prep_kernel<<<pgrid, 256>>>(
        (const float*)d_in[1], (const float*)d_in[3],
        (const float*)d_in[5], (const float*)d_in[7]);

    rnn_stack_kernel<<<NCTA, NTHR, SM_TOTAL>>>(
        (const float*)d_in[0],
        (const float*)d_in[2], (const float*)d_in[4],
        (const float*)d_in[6], (const float*)d_in[8],
        (const float*)d_in[9], (const float*)d_in[10],
        (float*)d_out);
}

// round 16
// speedup vs baseline: 1.0191x; 1.0191x over previous
#include <cuda_runtime.h>
#include <math.h>

// ---------------------------------------------------------------------------
// DilatedSparseRnnStack — R14: symmetric CTA pairs, 16 rows/group, K-split.
// Each CTA of a pair reads only HALF the weights (chip weight traffic
// 805 -> 403 MB/step, dropping below the measured LTS cap that bound R8-R13).
// Rank r handles k-half r of all 1024 gate-cols for 16 batch rows; k-partials
// for the partner-owned 8 rows are exchanged through an L2 box with windowed
// monotonic flags (symmetric, near-zero skew). Epilogue ownership by rows:
// rank0 rows 0-7, rank1 rows 8-15. out-section lives entirely in rank0's
// k-half; rank1 publishes its out rows via g_out. fp32 math unchanged.
// ---------------------------------------------------------------------------

namespace {
constexpr int T_STEPS = 256;
constexpr int BATCH   = 1024;
constexpr int IN_F    = 64;
constexpr int HSZ     = 128;
constexpr int OSZ     = 128;
constexpr int OUT_F   = 8;
constexpr int RPG     = 16;             // rows per group
constexpr int NGRP    = BATCH / RPG;    // 64
constexpr int NCTA    = NGRP * 2;       // 128
constexpr int NTHR    = 512;
constexpr int KTOT    = 320 + 384 + 448 + 384;  // 1536

// dynamic SMEM layout (bytes); xh buffer holds this CTA's k-half: [kloc][16 r]
constexpr int SM_XH0   = 0;        // 224*64 = 14336 (max K/2)
constexpr int SM_XH1   = 14336;
constexpr int SM_RED   = 28672;    // 256 j * 2 gp * 4 ull * 8B = 16384
constexpr int SM_OUT   = 45056;    // 128*8*4 = 4096 (own 8 rows)
constexpr int SM_WOUT  = 49152;    // 4096
constexpr int SM_TOTAL = 53248;
}

// Weights, transposed + gate-pair interleaved:
// float at WTOFF + ((k*2 + gp)*256 + j)*2 + gl   (gate g = 2*gp + gl)
// padded 8192 floats so the ring prefetch may harmlessly over-read.
__device__ float g_WT2[(size_t)KTOT * 1024 + 8192];

// Dilation buffers, group-local (slot offsets {0,1,4,10}, sizes {1,3,6,12}):
//   C: [slot 22][group 64][j 256][r 16]  (float4 quad rq = rows 4rq..4rq+3)
//   H: [slot 22][group 64][jh 128][r 16]
__device__ float4 g_bufC4[(size_t)22 * 64 * 256 * 4];
__device__ float4 g_bufH4[(size_t)22 * 64 * 128 * 4];

// out exchange (rank1 -> rank0): [group][j 128][quad 2] (rows 8-11, 12-15)
__device__ float4 g_out4[(size_t)64 * 128 * 2];

// k-partials exchange: [group][src 2][gp*256+j][8 ull]
__device__ unsigned long long g_part[(size_t)64 * 2 * 512 * 8];

// lockstep counters (monotonic within a launch; windowed reads)
__device__ int g_cntP[64][2];
__device__ int g_cntE[64][2];

__device__ __forceinline__ float sigf(float v) {
    return __fdividef(1.0f, 1.0f + __expf(-v));
}
__device__ __forceinline__ float tanh_fast(float v) {
    return __fdividef(2.0f, 1.0f + __expf(-2.0f * v)) - 1.0f;
}
__device__ __forceinline__ void ffma2(unsigned long long& d,
                                      unsigned long long a,
                                      unsigned long long b) {
    asm("fma.rn.f32x2 %0, %1, %2, %0;" : "+l"(d) : "l"(a), "l"(b));
}
__device__ __forceinline__ void fadd2(unsigned long long& d,
                                      unsigned long long a) {
    asm("add.rn.f32x2 %0, %0, %1;" : "+l"(d) : "l"(a));
}
__device__ __forceinline__ unsigned long long dup2(float w) {
    unsigned long long r;
    asm("mov.b64 %0, {%1, %1};" : "=l"(r) : "f"(w));
    return r;
}
__device__ __forceinline__ float2 u2f2(unsigned long long v) {
    float2 f;
    asm("mov.b64 {%0, %1}, %2;" : "=f"(f.x), "=f"(f.y) : "l"(v));
    return f;
}
// all threads spin; windowed check rejects stale cross-replay values (max 1024)
__device__ __forceinline__ void spin_ge(const int* f, int need) {
    unsigned it = 0;
    int v;
    do {
        asm volatile("ld.acquire.gpu.b32 %0, [%1];" : "=r"(v) : "l"(f));
        if (v >= need && v < need + 256) return;
    } while (++it < (1u << 22));
}
__device__ __forceinline__ void set_flag(int* f, int v) {
    asm volatile("st.release.gpu.b32 [%0], %1;" :: "l"(f), "r"(v) : "memory");
}

// ---------------------------------------------------------------------------
// Prep: transpose + gate-pair interleave weights.
// ---------------------------------------------------------------------------
__global__ void prep_kernel(const float* __restrict__ W0,
                            const float* __restrict__ W1,
                            const float* __restrict__ W2,
                            const float* __restrict__ W3)
{
    const int li = blockIdx.y;
    const float* W;
    int K, off;
    if (li == 0)      { W = W0; K = 320; off = 0; }
    else if (li == 1) { W = W1; K = 384; off = 320 * 1024; }
    else if (li == 2) { W = W2; K = 448; off = 704 * 1024; }
    else              { W = W3; K = 384; off = 1152 * 1024; }

    int idx = blockIdx.x * 256 + threadIdx.x;
    if (idx < 1024 * K) {
        int row = idx / K;           // g*256 + j
        int k   = idx - row * K;
        int g = row >> 8, j = row & 255;
        g_WT2[(size_t)off + ((size_t)(k * 2 + (g >> 1)) * 256 + j) * 2 + (g & 1)]
            = W[idx];
    }
}

// ---------------------------------------------------------------------------
// staging helpers
// ---------------------------------------------------------------------------
__device__ __forceinline__ void stage_Hsec(
    float* __restrict__ xh, int tid, int group, int slot, bool zero,
    int C0, int C1, int DST)
{
    const int n4 = (C1 - C0) * 4;
    for (int e = tid; e < n4; e += NTHR) {
        int jh = C0 + (e >> 2), rq = e & 3;
        float4 v = make_float4(0.f, 0.f, 0.f, 0.f);
        if (!zero)
            v = g_bufH4[((size_t)(slot * 64 + group) * 128 + jh) * 4 + rq];
        *reinterpret_cast<float4*>(&xh[(DST + (jh - C0)) * 16 + rq * 4]) = v;
    }
}
__device__ __forceinline__ void stage_xsec(
    float* __restrict__ xh, int tid, const float4* __restrict__ xt4, int DST)
{
    if (tid < 256) {
        int c4 = tid >> 4, r = tid & 15;
        float4 v = xt4[r * 16 + c4];
        int b = (DST + 4 * c4) * 16 + r;
        xh[b]      = v.x;
        xh[b + 16] = v.y;
        xh[b + 32] = v.z;
        xh[b + 48] = v.w;
    }
}
__device__ __forceinline__ void stage_outsec(
    float* __restrict__ xh, int tid, int group)
{
    if (tid < 256) {
        int jo = tid >> 1, q = tid & 1;
        *reinterpret_cast<float4*>(&xh[jo * 16 + (2 + q) * 4]) =
            g_out4[(size_t)(group * 128 + jo) * 2 + q];
    }
}

// ---------------------------------------------------------------------------
// One layer step. thread: j = tid&255 (col), gp = tid>>8 (gate pair).
// This CTA computes k-half `rank` of all gates for 16 rows; owns rows
// [8*rank, 8*rank+8) for the epilogue.
// ---------------------------------------------------------------------------
template <int K, int DIL, int LOFF, int LI, int WTOFF>
__device__ __forceinline__ void do_layer(
    int t, int tid, int group, int rank,
    const float4* __restrict__ xt4,
    float4 bias,
    char* __restrict__ smem)
{
    const int prevSlot = LOFF + (t - 1 + DIL) % DIL;
    const int curSlot  = LOFF + (t % DIL);
    const int j    = tid & 255;
    const int gp   = tid >> 8;
    const int m    = 4 * t + LI;
    constexpr int KH = K / 2;

    float* xh = reinterpret_cast<float*>(smem + ((LI & 1) ? SM_XH1 : SM_XH0));
    unsigned long long* s_red =
        reinterpret_cast<unsigned long long*>(smem + SM_RED);
    float* s_out = reinterpret_cast<float*>(smem + SM_OUT);

    // ---- wait partner epilogue of phase m-1 (H / g_out / box-consume) ----
    if (m > 0) spin_ge(&g_cntE[group][1 - rank], m);

    // ---- C prefetch (own quad; written only by this thread historically) ----
    const int quad = 2 * rank + gp;
    const size_t cI = ((size_t)(curSlot  * 64 + group) * 256 + j) * 4 + quad;
    const size_t pI = ((size_t)(prevSlot * 64 + group) * 256 + j) * 4 + quad;
    float4 pC4 = make_float4(0.f, 0.f, 0.f, 0.f);
    float4 dC4 = make_float4(0.f, 0.f, 0.f, 0.f);
    if (t > 0)    pC4 = g_bufC4[pI];
    if (t >= DIL) dC4 = g_bufC4[cI];

    // ---- weight ring prologue (addresses independent of staging) ----
    const char* wp = reinterpret_cast<const char*>(g_WT2)
                   + (size_t)WTOFF * 4 + (size_t)j * 8 + (size_t)gp * 2048
                   + (size_t)rank * KH * 4096;
    float2 wr[8];
#pragma unroll
    for (int u = 0; u < 8; ++u)
        wr[u] = *reinterpret_cast<const float2*>(wp + u * 4096);

    // ---- stage this CTA's k-half of xh ----
    {
        const int slotD = (t >= DIL) ? curSlot : prevSlot;
        const bool z = (t == 0);
        if (rank == 0) {
            if (LI == 0) {
                stage_xsec(xh, tid, xt4, 0);
                stage_Hsec(xh, tid, group, prevSlot, z, 0, 96, 64);
            } else if (LI == 2) {
                stage_outsec(xh, tid, group);
                stage_xsec(xh, tid, xt4, 128);
                stage_Hsec(xh, tid, group, prevSlot, z, 0, 32, 192);
            } else {  // LI 1,3
                stage_outsec(xh, tid, group);
                stage_Hsec(xh, tid, group, prevSlot, z, 0, 64, 128);
            }
        } else {
            if (LI == 0) {
                stage_Hsec(xh, tid, group, prevSlot, z, 96, 128, 0);
                stage_Hsec(xh, tid, group, slotD,    z, 0, 128, 32);
            } else if (LI == 2) {
                stage_Hsec(xh, tid, group, prevSlot, z, 32, 128, 0);
                stage_Hsec(xh, tid, group, slotD,    z, 0, 128, 96);
            } else {
                stage_Hsec(xh, tid, group, prevSlot, z, 64, 128, 0);
                stage_Hsec(xh, tid, group, slotD,    z, 0, 128, 64);
            }
        }
    }

    __syncthreads();  // sync B: xh k-half complete (incl. direct out-writes)

    // ---- GEMM: gates {2gp,2gp+1} x 16 rows over k-half ----
    unsigned long long aL[8], aH[8];
#pragma unroll
    for (int p = 0; p < 8; ++p) { aL[p] = 0ull; aH[p] = 0ull; }

    {
        const char* xp = reinterpret_cast<const char*>(xh);
        for (int kb = 0; kb < KH; kb += 8) {
#pragma unroll
            for (int u = 0; u < 8; ++u) {
                float2 w = wr[u];
                wr[u] = *reinterpret_cast<const float2*>(wp + (u + 8) * 4096);
                unsigned long long wA = dup2(w.x);
                unsigned long long wB = dup2(w.y);
                ulonglong2 x0 = *reinterpret_cast<const ulonglong2*>(xp + u * 64);
                ulonglong2 x1 = *reinterpret_cast<const ulonglong2*>(xp + u * 64 + 16);
                ffma2(aL[0], wA, x0.x); ffma2(aH[0], wB, x0.x);
                ffma2(aL[1], wA, x0.y); ffma2(aH[1], wB, x0.y);
                ffma2(aL[2], wA, x1.x); ffma2(aH[2], wB, x1.x);
                ffma2(aL[3], wA, x1.y); ffma2(aH[3], wB, x1.y);
                ulonglong2 x2 = *reinterpret_cast<const ulonglong2*>(xp + u * 64 + 32);
                ulonglong2 x3 = *reinterpret_cast<const ulonglong2*>(xp + u * 64 + 48);
                ffma2(aL[4], wA, x2.x); ffma2(aH[4], wB, x2.x);
                ffma2(aL[5], wA, x2.y); ffma2(aH[5], wB, x2.y);
                ffma2(aL[6], wA, x3.x); ffma2(aH[6], wB, x3.x);
                ffma2(aL[7], wA, x3.y); ffma2(aH[7], wB, x3.y);
            }
            wp += 8 * 4096;
            xp += 8 * 64;
        }
    }

    // ---- publish partials for partner-owned row-pairs ----
    {
        const int pn = 4 * (1 - rank);
        ulonglong2* b2 = reinterpret_cast<ulonglong2*>(
            g_part + ((size_t)(group * 2 + rank) * 512 + gp * 256 + j) * 8);
        b2[0] = make_ulonglong2(aL[pn],     aL[pn + 1]);
        b2[1] = make_ulonglong2(aL[pn + 2], aL[pn + 3]);
        b2[2] = make_ulonglong2(aH[pn],     aH[pn + 1]);
        b2[3] = make_ulonglong2(aH[pn + 2], aH[pn + 3]);
    }
    __threadfence();
    __syncthreads();  // sync X: all partial STGs issued + fenced
    if (tid == 0) set_flag(&g_cntP[group][rank], m + 1);

    spin_ge(&g_cntP[group][1 - rank], m + 1);

    // ---- fold partner partials into my owned pairs ----
    {
        const int po = 4 * rank;
        const ulonglong2* b2 = reinterpret_cast<const ulonglong2*>(
            g_part + ((size_t)(group * 2 + (1 - rank)) * 512 + gp * 256 + j) * 8);
        ulonglong2 v0 = b2[0], v1 = b2[1], v2 = b2[2], v3 = b2[3];
        fadd2(aL[po],     v0.x); fadd2(aL[po + 1], v0.y);
        fadd2(aL[po + 2], v1.x); fadd2(aL[po + 3], v1.y);
        fadd2(aH[po],     v2.x); fadd2(aH[po + 1], v2.y);
        fadd2(aH[po + 2], v3.x); fadd2(aH[po + 3], v3.y);
    }

    // ---- intra-CTA gate regroup via s_red ----
    {
        const int pw = 4 * rank + 2 * (1 - gp);   // other sub-owner's pairs
        ulonglong2* r2 = reinterpret_cast<ulonglong2*>(
            s_red + (size_t)(j * 2 + gp) * 4);
        r2[0] = make_ulonglong2(aL[pw], aL[pw + 1]);
        r2[1] = make_ulonglong2(aH[pw], aH[pw + 1]);
    }
    __syncthreads();  // sync D
    unsigned long long oG0, oG1, oG2, oG3;
    {
        const ulonglong2* r2 = reinterpret_cast<const ulonglong2*>(
            s_red + (size_t)(j * 2 + (1 - gp)) * 4);
        ulonglong2 q0 = r2[0], q1 = r2[1];
        oG0 = q0.x; oG1 = q0.y; oG2 = q1.x; oG3 = q1.y;
    }

    // ---- select the 4 gates for my 2 owned pairs ----
    const int p0 = 4 * rank + 2 * gp;
    unsigned long long Gf[2], Gc[2], Ga[2], Go[2];
    if (gp == 0) {
        Gf[0] = aL[p0]; Gf[1] = aL[p0 + 1];
        Gc[0] = aH[p0]; Gc[1] = aH[p0 + 1];
        Ga[0] = oG0;    Ga[1] = oG1;
        Go[0] = oG2;    Go[1] = oG3;
    } else {
        Ga[0] = aL[p0]; Ga[1] = aL[p0 + 1];
        Go[0] = aH[p0]; Go[1] = aH[p0 + 1];
        Gf[0] = oG0;    Gf[1] = oG1;
        Gc[0] = oG2;    Gc[1] = oG3;
    }

    // ---- epilogue: 4 rows (quad) of col j ----
    const float* pCf = &pC4.x;
    const float* dCf = &dC4.x;
    float nc[4], wh[4];
#pragma unroll
    for (int i = 0; i < 2; ++i) {
        float2 g0 = u2f2(Gf[i]);
        float2 g1 = u2f2(Gc[i]);
        float2 g2 = u2f2(Ga[i]);
        float2 g3 = u2f2(Go[i]);
#pragma unroll
        for (int s = 0; s < 2; ++s) {
            const int r = 2 * i + s;
            float forget = sigf((s ? g0.y : g0.x) + bias.x + 1.0f);
            float cand   = tanh_fast((s ? g1.y : g1.x) + bias.y);
            float alpha  = sigf((s ? g2.y : g2.x) + bias.z);
            float og     = sigf((s ? g3.y : g3.x) + bias.w);
            float newC;
            if (t == 0) {
                newC = cand;
            } else {
                float wC = pCf[r];
                if (t >= DIL) {
                    wC = alpha * pCf[r] + (1.0f - alpha) * dCf[r];
                }
                newC = forget * wC + (1.0f - forget) * cand;
            }
            nc[r] = newC;
            wh[r] = og * newC;
        }
    }
    g_bufC4[cI] = make_float4(nc[0], nc[1], nc[2], nc[3]);
    float4 w4 = make_float4(wh[0], wh[1], wh[2], wh[3]);
    if (j < OSZ) {
        if (LI < 3) {
            if (rank == 0) {
                // own rows 0-7 (quads 0,1) directly into next xh buffer
                float* xn = reinterpret_cast<float*>(
                    smem + ((LI & 1) ? SM_XH0 : SM_XH1));
                *reinterpret_cast<float4*>(&xn[j * 16 + quad * 4]) = w4;
            } else {
                g_out4[(size_t)(group * 128 + j) * 2 + gp] = w4;
            }
        } else {
            *reinterpret_cast<float4*>(&s_out[j * 8 + gp * 4]) = w4;
        }
    } else {
        g_bufH4[((size_t)(curSlot * 64 + group) * 128 + (j - OSZ)) * 4 + quad] = w4;
    }

    __threadfence();
    __syncthreads();  // sync F: all epilogue STGs issued + fenced
    if (tid == 0) set_flag(&g_cntE[group][rank], m + 1);
}

__global__ __launch_bounds__(NTHR, 1) void rnn_stack_kernel(
    const float* __restrict__ x,
    const float* __restrict__ b0, const float* __restrict__ b1,
    const float* __restrict__ b2, const float* __restrict__ b3,
    const float* __restrict__ Wout, const float* __restrict__ bout,
    float* __restrict__ out)
{
    extern __shared__ char smem[];
    float* s_out  = reinterpret_cast<float*>(smem + SM_OUT);
    float* s_wout = reinterpret_cast<float*>(smem + SM_WOUT);

    const int tid   = threadIdx.x;
    const int group = blockIdx.x >> 1;
    const int rank  = blockIdx.x & 1;
    const int row0  = group * RPG;
    const int j     = tid & 255;

    // reset own counters for this launch/replay
    if (tid == 0) {
        g_cntP[group][rank] = 0;
        g_cntE[group][rank] = 0;
        __threadfence();
    }

    if (tid < 256) {
        reinterpret_cast<float4*>(s_wout)[tid] =
            reinterpret_cast<const float4*>(Wout)[tid];
    }
    float4 bs0 = make_float4(b0[j], b0[256 + j], b0[512 + j], b0[768 + j]);
    float4 bs1 = make_float4(b1[j], b1[256 + j], b1[512 + j], b1[768 + j]);
    float4 bs2 = make_float4(b2[j], b2[256 + j], b2[512 + j], b2[768 + j]);
    float4 bs3 = make_float4(b3[j], b3[256 + j], b3[512 + j], b3[768 + j]);

    // projection mapping over own 8 rows: seg=tid&7, o=(tid>>3)&7, r=tid>>6
    const int p_seg = tid & 7;
    const int p_o   = (tid >> 3) & 7;
    const int p_r   = tid >> 6;
    const float bo  = bout[p_o];

    __syncthreads();  // counters reset + s_wout staged

    for (int t = 0; t < T_STEPS; ++t) {
        const float4* xt4 = reinterpret_cast<const float4*>(
            x + ((size_t)t * BATCH + row0) * IN_F);

        do_layer<320,  1,  0, 0, 0>          (t, tid, group, rank, xt4, bs0, smem);
        do_layer<384,  3,  1, 1, 320 * 1024> (t, tid, group, rank, xt4, bs1, smem);
        do_layer<448,  6,  4, 2, 704 * 1024> (t, tid, group, rank, xt4, bs2, smem);
        do_layer<384, 12, 10, 3, 1152 * 1024>(t, tid, group, rank, xt4, bs3, smem);

        // ---- output projection over own 8 rows (s_out fenced by sync F) ----
        {
            float acc = 0.f;
#pragma unroll
            for (int qq = 0; qq < 16; ++qq) {
                int qv = qq * 8 + p_seg;
                acc = fmaf(s_out[qv * 8 + p_r], s_wout[p_o * OSZ + qv], acc);
            }
            acc += __shfl_down_sync(0xffffffffu, acc, 4, 8);
            acc += __shfl_down_sync(0xffffffffu, acc, 2, 8);
            acc += __shfl_down_sync(0xffffffffu, acc, 1, 8);
            if (p_seg == 0) {
                out[((size_t)t * BATCH + row0 + 8 * rank + p_r) * OUT_F + p_o]
                    = acc + bo;
            }
        }
    }
}

extern "C" void kernel_launch(void* const* d_in, const int* in_sizes, int n_in,
                              void* d_out, int out_size)
{
    (void)in_sizes; (void)n_in; (void)out_size;

    cudaFuncSetAttribute(rnn_stack_kernel,
                         cudaFuncAttributeMaxDynamicSharedMemorySize, SM_TOTAL);

    dim3 pgrid((1024 * 448 + 255) / 256, 4);
    prep_kernel<<<pgrid, 256>>>(
        (const float*)d_in[1], (const float*)d_in[3],
        (const float*)d_in[5], (const float*)d_in[7]);

    rnn_stack_kernel<<<NCTA, NTHR, SM_TOTAL>>>(
        (const float*)d_in[0],
        (const float*)d_in[2], (const float*)d_in[4],
        (const float*)d_in[6], (const float*)d_in[8],
        (const float*)d_in[9], (const float*)d_in[10],
        (float*)d_out);
}

// round 17
// speedup vs baseline: 1.0331x; 1.0137x over previous
#include <cuda_runtime.h>
#include <math.h>

// ---------------------------------------------------------------------------
// DilatedSparseRnnStack — R17: R14 (symmetric CTA pairs, K-split, halved
// weight stream) with the spin protocol fixed:
//   * only tid 0 spins, CTA waits behind __syncthreads (no 512-thread storm)
//   * flags padded to 128B lines (no cross-group false sharing)
//   * __nanosleep backoff in the poll loop
//   * weight-ring prologue + own-C prefetch issued BEFORE the partner wait
// Everything else (layout, exchange, epilogue, math) identical to R14, which
// was bit-correct (rel_err 8.3e-7).
// ---------------------------------------------------------------------------

namespace {
constexpr int T_STEPS = 256;
constexpr int BATCH   = 1024;
constexpr int IN_F    = 64;
constexpr int HSZ     = 128;
constexpr int OSZ     = 128;
constexpr int OUT_F   = 8;
constexpr int RPG     = 16;             // rows per group
constexpr int NGRP    = BATCH / RPG;    // 64
constexpr int NCTA    = NGRP * 2;       // 128
constexpr int NTHR    = 512;
constexpr int KTOT    = 320 + 384 + 448 + 384;  // 1536

// dynamic SMEM layout (bytes); xh buffer holds this CTA's k-half: [kloc][16 r]
constexpr int SM_XH0   = 0;        // 224*64 = 14336 (max K/2)
constexpr int SM_XH1   = 14336;
constexpr int SM_RED   = 28672;    // 16384
constexpr int SM_OUT   = 45056;    // 4096
constexpr int SM_WOUT  = 49152;    // 4096
constexpr int SM_TOTAL = 53248;
}

// Weights, transposed + gate-pair interleaved:
// float at WTOFF + ((k*2 + gp)*256 + j)*2 + gl   (gate g = 2*gp + gl)
__device__ float g_WT2[(size_t)KTOT * 1024 + 8192];

// Dilation buffers, group-local (slot offsets {0,1,4,10}, sizes {1,3,6,12}):
//   C: [slot 22][group 64][j 256][r 16]  (float4 quad rq = rows 4rq..4rq+3)
//   H: [slot 22][group 64][jh 128][r 16]
__device__ float4 g_bufC4[(size_t)22 * 64 * 256 * 4];
__device__ float4 g_bufH4[(size_t)22 * 64 * 128 * 4];

// out exchange (rank1 -> rank0): [group][j 128][quad 2]
__device__ float4 g_out4[(size_t)64 * 128 * 2];

// k-partials exchange: [group][src 2][gp*256+j][8 ull]
__device__ unsigned long long g_part[(size_t)64 * 2 * 512 * 8];

// lockstep counters, one 128B line each: [group][rank][32 ints]
__device__ int g_cntP[64][2][32];
__device__ int g_cntE[64][2][32];

__device__ __forceinline__ float sigf(float v) {
    return __fdividef(1.0f, 1.0f + __expf(-v));
}
__device__ __forceinline__ float tanh_fast(float v) {
    return __fdividef(2.0f, 1.0f + __expf(-2.0f * v)) - 1.0f;
}
__device__ __forceinline__ void ffma2(unsigned long long& d,
                                      unsigned long long a,
                                      unsigned long long b) {
    asm("fma.rn.f32x2 %0, %1, %2, %0;" : "+l"(d) : "l"(a), "l"(b));
}
__device__ __forceinline__ void fadd2(unsigned long long& d,
                                      unsigned long long a) {
    asm("add.rn.f32x2 %0, %0, %1;" : "+l"(d) : "l"(a));
}
__device__ __forceinline__ unsigned long long dup2(float w) {
    unsigned long long r;
    asm("mov.b64 %0, {%1, %1};" : "=l"(r) : "f"(w));
    return r;
}
__device__ __forceinline__ float2 u2f2(unsigned long long v) {
    float2 f;
    asm("mov.b64 {%0, %1}, %2;" : "=f"(f.x), "=f"(f.y) : "l"(v));
    return f;
}
// tid0-only spin; windowed check rejects stale cross-replay values.
__device__ __forceinline__ void spin_ge(const int* f, int need) {
    unsigned it = 0;
    int v;
    do {
        asm volatile("ld.acquire.gpu.b32 %0, [%1];" : "=r"(v) : "l"(f));
        if (v >= need && v < need + 256) return;
        if (++it > 8) __nanosleep(64);
    } while (it < (1u << 22));
}
__device__ __forceinline__ void set_flag(int* f, int v) {
    asm volatile("st.release.gpu.b32 [%0], %1;" :: "l"(f), "r"(v) : "memory");
}

// ---------------------------------------------------------------------------
// Prep: transpose + gate-pair interleave weights.
// ---------------------------------------------------------------------------
__global__ void prep_kernel(const float* __restrict__ W0,
                            const float* __restrict__ W1,
                            const float* __restrict__ W2,
                            const float* __restrict__ W3)
{
    const int li = blockIdx.y;
    const float* W;
    int K, off;
    if (li == 0)      { W = W0; K = 320; off = 0; }
    else if (li == 1) { W = W1; K = 384; off = 320 * 1024; }
    else if (li == 2) { W = W2; K = 448; off = 704 * 1024; }
    else              { W = W3; K = 384; off = 1152 * 1024; }

    int idx = blockIdx.x * 256 + threadIdx.x;
    if (idx < 1024 * K) {
        int row = idx / K;           // g*256 + j
        int k   = idx - row * K;
        int g = row >> 8, j = row & 255;
        g_WT2[(size_t)off + ((size_t)(k * 2 + (g >> 1)) * 256 + j) * 2 + (g & 1)]
            = W[idx];
    }
}

// ---------------------------------------------------------------------------
// staging helpers
// ---------------------------------------------------------------------------
__device__ __forceinline__ void stage_Hsec(
    float* __restrict__ xh, int tid, int group, int slot, bool zero,
    int C0, int C1, int DST)
{
    const int n4 = (C1 - C0) * 4;
    for (int e = tid; e < n4; e += NTHR) {
        int jh = C0 + (e >> 2), rq = e & 3;
        float4 v = make_float4(0.f, 0.f, 0.f, 0.f);
        if (!zero)
            v = g_bufH4[((size_t)(slot * 64 + group) * 128 + jh) * 4 + rq];
        *reinterpret_cast<float4*>(&xh[(DST + (jh - C0)) * 16 + rq * 4]) = v;
    }
}
__device__ __forceinline__ void stage_xsec(
    float* __restrict__ xh, int tid, const float4* __restrict__ xt4, int DST)
{
    if (tid < 256) {
        int c4 = tid >> 4, r = tid & 15;
        float4 v = xt4[r * 16 + c4];
        int b = (DST + 4 * c4) * 16 + r;
        xh[b]      = v.x;
        xh[b + 16] = v.y;
        xh[b + 32] = v.z;
        xh[b + 48] = v.w;
    }
}
__device__ __forceinline__ void stage_outsec(
    float* __restrict__ xh, int tid, int group)
{
    if (tid < 256) {
        int jo = tid >> 1, q = tid & 1;
        *reinterpret_cast<float4*>(&xh[jo * 16 + (2 + q) * 4]) =
            g_out4[(size_t)(group * 128 + jo) * 2 + q];
    }
}

// ---------------------------------------------------------------------------
// One layer step. thread: j = tid&255 (col), gp = tid>>8 (gate pair).
// CTA computes k-half `rank` of all gates for 16 rows; owns rows
// [8*rank, 8*rank+8) for the epilogue.
// ---------------------------------------------------------------------------
template <int K, int DIL, int LOFF, int LI, int WTOFF>
__device__ __forceinline__ void do_layer(
    int t, int tid, int group, int rank,
    const float4* __restrict__ xt4,
    float4 bias,
    char* __restrict__ smem)
{
    const int prevSlot = LOFF + (t - 1 + DIL) % DIL;
    const int curSlot  = LOFF + (t % DIL);
    const int j    = tid & 255;
    const int gp   = tid >> 8;
    const int m    = 4 * t + LI;
    constexpr int KH = K / 2;

    float* xh = reinterpret_cast<float*>(smem + ((LI & 1) ? SM_XH1 : SM_XH0));
    unsigned long long* s_red =
        reinterpret_cast<unsigned long long*>(smem + SM_RED);
    float* s_out = reinterpret_cast<float*>(smem + SM_OUT);

    // ---- independent-of-partner loads FIRST (latency hides under spin) ----
    // weight ring prologue
    const char* wp = reinterpret_cast<const char*>(g_WT2)
                   + (size_t)WTOFF * 4 + (size_t)j * 8 + (size_t)gp * 2048
                   + (size_t)rank * KH * 4096;
    float2 wr[8];
#pragma unroll
    for (int u = 0; u < 8; ++u)
        wr[u] = *reinterpret_cast<const float2*>(wp + u * 4096);

    // C prefetch (own quad; written only by this thread historically)
    const int quad = 2 * rank + gp;
    const size_t cI = ((size_t)(curSlot  * 64 + group) * 256 + j) * 4 + quad;
    const size_t pI = ((size_t)(prevSlot * 64 + group) * 256 + j) * 4 + quad;
    float4 pC4 = make_float4(0.f, 0.f, 0.f, 0.f);
    float4 dC4 = make_float4(0.f, 0.f, 0.f, 0.f);
    if (t > 0)    pC4 = g_bufC4[pI];
    if (t >= DIL) dC4 = g_bufC4[cI];

    // ---- wait partner epilogue of phase m-1 (tid0 only, then barrier) ----
    if (m > 0) {
        if (tid == 0) spin_ge(&g_cntE[group][1 - rank][0], m);
        __syncthreads();
    }

    // ---- stage this CTA's k-half of xh ----
    {
        const int slotD = (t >= DIL) ? curSlot : prevSlot;
        const bool z = (t == 0);
        if (rank == 0) {
            if (LI == 0) {
                stage_xsec(xh, tid, xt4, 0);
                stage_Hsec(xh, tid, group, prevSlot, z, 0, 96, 64);
            } else if (LI == 2) {
                stage_outsec(xh, tid, group);
                stage_xsec(xh, tid, xt4, 128);
                stage_Hsec(xh, tid, group, prevSlot, z, 0, 32, 192);
            } else {  // LI 1,3
                stage_outsec(xh, tid, group);
                stage_Hsec(xh, tid, group, prevSlot, z, 0, 64, 128);
            }
        } else {
            if (LI == 0) {
                stage_Hsec(xh, tid, group, prevSlot, z, 96, 128, 0);
                stage_Hsec(xh, tid, group, slotD,    z, 0, 128, 32);
            } else if (LI == 2) {
                stage_Hsec(xh, tid, group, prevSlot, z, 32, 128, 0);
                stage_Hsec(xh, tid, group, slotD,    z, 0, 128, 96);
            } else {
                stage_Hsec(xh, tid, group, prevSlot, z, 64, 128, 0);
                stage_Hsec(xh, tid, group, slotD,    z, 0, 128, 64);
            }
        }
    }

    __syncthreads();  // sync B: xh k-half complete (incl. direct out-writes)

    // ---- GEMM: gates {2gp,2gp+1} x 16 rows over k-half ----
    unsigned long long aL[8], aH[8];
#pragma unroll
    for (int p = 0; p < 8; ++p) { aL[p] = 0ull; aH[p] = 0ull; }

    {
        const char* xp = reinterpret_cast<const char*>(xh);
        for (int kb = 0; kb < KH; kb += 8) {
#pragma unroll
            for (int u = 0; u < 8; ++u) {
                float2 w = wr[u];
                wr[u] = *reinterpret_cast<const float2*>(wp + (u + 8) * 4096);
                unsigned long long wA = dup2(w.x);
                unsigned long long wB = dup2(w.y);
                ulonglong2 x0 = *reinterpret_cast<const ulonglong2*>(xp + u * 64);
                ulonglong2 x1 = *reinterpret_cast<const ulonglong2*>(xp + u * 64 + 16);
                ffma2(aL[0], wA, x0.x); ffma2(aH[0], wB, x0.x);
                ffma2(aL[1], wA, x0.y); ffma2(aH[1], wB, x0.y);
                ffma2(aL[2], wA, x1.x); ffma2(aH[2], wB, x1.x);
                ffma2(aL[3], wA, x1.y); ffma2(aH[3], wB, x1.y);
                ulonglong2 x2 = *reinterpret_cast<const ulonglong2*>(xp + u * 64 + 32);
                ulonglong2 x3 = *reinterpret_cast<const ulonglong2*>(xp + u * 64 + 48);
                ffma2(aL[4], wA, x2.x); ffma2(aH[4], wB, x2.x);
                ffma2(aL[5], wA, x2.y); ffma2(aH[5], wB, x2.y);
                ffma2(aL[6], wA, x3.x); ffma2(aH[6], wB, x3.x);
                ffma2(aL[7], wA, x3.y); ffma2(aH[7], wB, x3.y);
            }
            wp += 8 * 4096;
            xp += 8 * 64;
        }
    }

    // ---- publish partials for partner-owned row-pairs ----
    {
        const int pn = 4 * (1 - rank);
        ulonglong2* b2 = reinterpret_cast<ulonglong2*>(
            g_part + ((size_t)(group * 2 + rank) * 512 + gp * 256 + j) * 8);
        b2[0] = make_ulonglong2(aL[pn],     aL[pn + 1]);
        b2[1] = make_ulonglong2(aL[pn + 2], aL[pn + 3]);
        b2[2] = make_ulonglong2(aH[pn],     aH[pn + 1]);
        b2[3] = make_ulonglong2(aH[pn + 2], aH[pn + 3]);
    }
    __threadfence();
    __syncthreads();  // sync X: all partial STGs issued + fenced
    if (tid == 0) {
        set_flag(&g_cntP[group][rank][0], m + 1);
        spin_ge(&g_cntP[group][1 - rank][0], m + 1);
    }
    __syncthreads();  // partner partials visible

    // ---- fold partner partials into my owned pairs ----
    {
        const int po = 4 * rank;
        const ulonglong2* b2 = reinterpret_cast<const ulonglong2*>(
            g_part + ((size_t)(group * 2 + (1 - rank)) * 512 + gp * 256 + j) * 8);
        ulonglong2 v0 = b2[0], v1 = b2[1], v2 = b2[2], v3 = b2[3];
        fadd2(aL[po],     v0.x); fadd2(aL[po + 1], v0.y);
        fadd2(aL[po + 2], v1.x); fadd2(aL[po + 3], v1.y);
        fadd2(aH[po],     v2.x); fadd2(aH[po + 1], v2.y);
        fadd2(aH[po + 2], v3.x); fadd2(aH[po + 3], v3.y);
    }

    // ---- intra-CTA gate regroup via s_red ----
    {
        const int pw = 4 * rank + 2 * (1 - gp);   // other sub-owner's pairs
        ulonglong2* r2 = reinterpret_cast<ulonglong2*>(
            s_red + (size_t)(j * 2 + gp) * 4);
        r2[0] = make_ulonglong2(aL[pw], aL[pw + 1]);
        r2[1] = make_ulonglong2(aH[pw], aH[pw + 1]);
    }
    __syncthreads();  // sync D
    unsigned long long oG0, oG1, oG2, oG3;
    {
        const ulonglong2* r2 = reinterpret_cast<const ulonglong2*>(
            s_red + (size_t)(j * 2 + (1 - gp)) * 4);
        ulonglong2 q0 = r2[0], q1 = r2[1];
        oG0 = q0.x; oG1 = q0.y; oG2 = q1.x; oG3 = q1.y;
    }

    // ---- select the 4 gates for my 2 owned pairs ----
    const int p0 = 4 * rank + 2 * gp;
    unsigned long long Gf[2], Gc[2], Ga[2], Go[2];
    if (gp == 0) {
        Gf[0] = aL[p0]; Gf[1] = aL[p0 + 1];
        Gc[0] = aH[p0]; Gc[1] = aH[p0 + 1];
        Ga[0] = oG0;    Ga[1] = oG1;
        Go[0] = oG2;    Go[1] = oG3;
    } else {
        Ga[0] = aL[p0]; Ga[1] = aL[p0 + 1];
        Go[0] = aH[p0]; Go[1] = aH[p0 + 1];
        Gf[0] = oG0;    Gf[1] = oG1;
        Gc[0] = oG2;    Gc[1] = oG3;
    }

    // ---- epilogue: 4 rows (quad) of col j ----
    const float* pCf = &pC4.x;
    const float* dCf = &dC4.x;
    float nc[4], wh[4];
#pragma unroll
    for (int i = 0; i < 2; ++i) {
        float2 g0 = u2f2(Gf[i]);
        float2 g1 = u2f2(Gc[i]);
        float2 g2 = u2f2(Ga[i]);
        float2 g3 = u2f2(Go[i]);
#pragma unroll
        for (int s = 0; s < 2; ++s) {
            const int r = 2 * i + s;
            float forget = sigf((s ? g0.y : g0.x) + bias.x + 1.0f);
            float cand   = tanh_fast((s ? g1.y : g1.x) + bias.y);
            float alpha  = sigf((s ? g2.y : g2.x) + bias.z);
            float og     = sigf((s ? g3.y : g3.x) + bias.w);
            float newC;
            if (t == 0) {
                newC = cand;
            } else {
                float wC = pCf[r];
                if (t >= DIL) {
                    wC = alpha * pCf[r] + (1.0f - alpha) * dCf[r];
                }
                newC = forget * wC + (1.0f - forget) * cand;
            }
            nc[r] = newC;
            wh[r] = og * newC;
        }
    }
    g_bufC4[cI] = make_float4(nc[0], nc[1], nc[2], nc[3]);
    float4 w4 = make_float4(wh[0], wh[1], wh[2], wh[3]);
    if (j < OSZ) {
        if (LI < 3) {
            if (rank == 0) {
                float* xn = reinterpret_cast<float*>(
                    smem + ((LI & 1) ? SM_XH0 : SM_XH1));
                *reinterpret_cast<float4*>(&xn[j * 16 + quad * 4]) = w4;
            } else {
                g_out4[(size_t)(group * 128 + j) * 2 + gp] = w4;
            }
        } else {
            *reinterpret_cast<float4*>(&s_out[j * 8 + gp * 4]) = w4;
        }
    } else {
        g_bufH4[((size_t)(curSlot * 64 + group) * 128 + (j - OSZ)) * 4 + quad] = w4;
    }

    __threadfence();
    __syncthreads();  // sync F: all epilogue STGs issued + fenced
    if (tid == 0) set_flag(&g_cntE[group][rank][0], m + 1);
}

__global__ __launch_bounds__(NTHR, 1) void rnn_stack_kernel(
    const float* __restrict__ x,
    const float* __restrict__ b0, const float* __restrict__ b1,
    const float* __restrict__ b2, const float* __restrict__ b3,
    const float* __restrict__ Wout, const float* __restrict__ bout,
    float* __restrict__ out)
{
    extern __shared__ char smem[];
    float* s_out  = reinterpret_cast<float*>(smem + SM_OUT);
    float* s_wout = reinterpret_cast<float*>(smem + SM_WOUT);

    const int tid   = threadIdx.x;
    const int group = blockIdx.x >> 1;
    const int rank  = blockIdx.x & 1;
    const int row0  = group * RPG;
    const int j     = tid & 255;

    // reset own counters for this launch/replay
    if (tid == 0) {
        g_cntP[group][rank][0] = 0;
        g_cntE[group][rank][0] = 0;
        __threadfence();
    }

    if (tid < 256) {
        reinterpret_cast<float4*>(s_wout)[tid] =
            reinterpret_cast<const float4*>(Wout)[tid];
    }
    float4 bs0 = make_float4(b0[j], b0[256 + j], b0[512 + j], b0[768 + j]);
    float4 bs1 = make_float4(b1[j], b1[256 + j], b1[512 + j], b1[768 + j]);
    float4 bs2 = make_float4(b2[j], b2[256 + j], b2[512 + j], b2[768 + j]);
    float4 bs3 = make_float4(b3[j], b3[256 + j], b3[512 + j], b3[768 + j]);

    // projection mapping over own 8 rows: seg=tid&7, o=(tid>>3)&7, r=tid>>6
    const int p_seg = tid & 7;
    const int p_o   = (tid >> 3) & 7;
    const int p_r   = tid >> 6;
    const float bo  = bout[p_o];

    __syncthreads();  // counters reset + s_wout staged

    for (int t = 0; t < T_STEPS; ++t) {
        const float4* xt4 = reinterpret_cast<const float4*>(
            x + ((size_t)t * BATCH + row0) * IN_F);

        do_layer<320,  1,  0, 0, 0>          (t, tid, group, rank, xt4, bs0, smem);
        do_layer<384,  3,  1, 1, 320 * 1024> (t, tid, group, rank, xt4, bs1, smem);
        do_layer<448,  6,  4, 2, 704 * 1024> (t, tid, group, rank, xt4, bs2, smem);
        do_layer<384, 12, 10, 3, 1152 * 1024>(t, tid, group, rank, xt4, bs3, smem);

        // ---- output projection over own 8 rows (s_out fenced by sync F) ----
        {
            float acc = 0.f;
#pragma unroll
            for (int qq = 0; qq < 16; ++qq) {
                int qv = qq * 8 + p_seg;
                acc = fmaf(s_out[qv * 8 + p_r], s_wout[p_o * OSZ + qv], acc);
            }
            acc += __shfl_down_sync(0xffffffffu, acc, 4, 8);
            acc += __shfl_down_sync(0xffffffffu, acc, 2, 8);
            acc += __shfl_down_sync(0xffffffffu, acc, 1, 8);
            if (p_seg == 0) {
                out[((size_t)t * BATCH + row0 + 8 * rank + p_r) * OUT_F + p_o]
                    = acc + bo;
            }
        }
    }
}

extern "C" void kernel_launch(void* const* d_in, const int* in_sizes, int n_in,
                              void* d_out, int out_size)
{
    (void)in_sizes; (void)n_in; (void)out_size;

    cudaFuncSetAttribute(rnn_stack_kernel,
                         cudaFuncAttributeMaxDynamicSharedMemorySize, SM_TOTAL);

    dim3 pgrid((1024 * 448 + 255) / 256, 4);
    prep_kernel<<<pgrid, 256>>>(
        (const float*)d_in[1], (const float*)d_in[3],
        (const float*)d_in[5], (const float*)d_in[7]);

    rnn_stack_kernel<<<NCTA, NTHR, SM_TOTAL>>>(
        (const float*)d_in[0],
        (const float*)d_in[2], (const float*)d_in[4],
        (const float*)d_in[6], (const float*)d_in[8],
        (const float*)d_in[9], (const float*)d_in[10],
        (float*)d_out);
}